// round 1
// baseline (speedup 1.0000x reference)
#include <cuda_runtime.h>
#include <cstdint>

// LSTM_58514634440709: B=8, L=32768, H=96, 2 layers + linear head.
// 8 clusters x 3 CTAs. Cluster = one batch sequence, 3-stage pipeline:
//   CTA0: layer-0 recurrence (W_hh_0 rows in registers)      -> h0 stream
//   CTA1: u = W_ih_1 * h0 + b1 (W_ih_1 rows in registers)    -> u stream
//   CTA2: v = W_hh_1 * h1 ; gates1 = u + v ; h1, head output
// Weights are RF-resident (48 packed f32x2 regs per thread = one 96-wide row).
// Inter-CTA transport: DSMEM stores + mbarrier full/empty rings (4 slots).

#define H 96
#define G 384       // 4*H gate rows
#define BATCH 8
#define NSLOT 4

struct __align__(16) Smem {
    unsigned long long fullA[NSLOT];   // lives in CTA1 (h0 slots full)
    unsigned long long emptyA[NSLOT];  // lives in CTA0 (h0 slots free)
    unsigned long long fullB[NSLOT];   // lives in CTA2 (u slots full)
    unsigned long long emptyB[NSLOT];  // lives in CTA1 (u slots free)
    float slotA[NSLOT][H];             // CTA1: incoming h0
    float slotB[NSLOT][G];             // CTA2: incoming u
    float hloc[H];                     // CTA0: h0 state ; CTA2: h1 state
    float z[G];                        // gate pre-activations scratch
    float wpart[4];                    // head partial sums
};

__device__ __forceinline__ uint32_t saddr(const void* p) {
    return (uint32_t)__cvta_generic_to_shared(p);
}
__device__ __forceinline__ uint32_t mapa_rank(uint32_t a, uint32_t r) {
    uint32_t d;
    asm("mapa.shared::cluster.u32 %0, %1, %2;" : "=r"(d) : "r"(a), "r"(r));
    return d;
}
__device__ __forceinline__ void mbar_init(uint32_t a, uint32_t cnt) {
    asm volatile("mbarrier.init.shared.b64 [%0], %1;" :: "r"(a), "r"(cnt) : "memory");
}
__device__ __forceinline__ void arrive_remote(uint32_t a) {
    asm volatile("mbarrier.arrive.release.cluster.shared::cluster.b64 _, [%0];"
                 :: "r"(a) : "memory");
}
__device__ __forceinline__ void st_remote(uint32_t a, float v) {
    asm volatile("st.shared::cluster.b32 [%0], %1;"
                 :: "r"(a), "r"(__float_as_uint(v)) : "memory");
}
// Wait on local mbarrier, acquire at cluster scope (data was written via DSMEM).
__device__ __forceinline__ void wait_par(uint32_t a, uint32_t par) {
    asm volatile(
        "{\n\t"
        ".reg .pred P;\n\t"
        "WLOOP_%=:\n\t"
        "mbarrier.try_wait.parity.acquire.cluster.shared::cta.b64 P, [%0], %1, 0x989680;\n\t"
        "@P bra WDONE_%=;\n\t"
        "bra WLOOP_%=;\n\t"
        "WDONE_%=:\n\t"
        "}" :: "r"(a), "r"(par) : "memory");
}

#define FMA2(acc, w, h) asm("fma.rn.f32x2 %0, %1, %2, %0;" : "+l"(acc) : "l"(w), "l"(h))
#define ADD2(a, b)      asm("add.rn.f32x2 %0, %0, %1;" : "+l"(a) : "l"(b))

__device__ __forceinline__ float sigf(float x) {
    return __fdividef(1.f, 1.f + __expf(-x));
}
__device__ __forceinline__ float tanh_fast(float x) {
    // 2*sigmoid(2x)-1 ; saturates correctly via exp overflow -> inf -> 0
    return __fmaf_rn(2.f, __fdividef(1.f, 1.f + __expf(-2.f * x)), -1.f);
}

// dot(w_row[96], h[96]) with packed f32x2 FMAs; h is 16B-aligned smem.
__device__ __forceinline__ float dot96(const unsigned long long* w2, const float* h) {
    const ulonglong2* h2 = (const ulonglong2*)h;
    unsigned long long a0 = 0ull, a1 = 0ull, a2 = 0ull, a3 = 0ull;
#pragma unroll
    for (int k = 0; k < 12; k++) {
        ulonglong2 p = h2[2 * k];
        ulonglong2 q = h2[2 * k + 1];
        FMA2(a0, w2[4 * k + 0], p.x);
        FMA2(a1, w2[4 * k + 1], p.y);
        FMA2(a2, w2[4 * k + 2], q.x);
        FMA2(a3, w2[4 * k + 3], q.y);
    }
    ADD2(a0, a1); ADD2(a2, a3); ADD2(a0, a2);
    float lo = __uint_as_float((unsigned)(a0 & 0xffffffffull));
    float hi = __uint_as_float((unsigned)(a0 >> 32));
    return lo + hi;
}

__global__ void __cluster_dims__(3, 1, 1) __launch_bounds__(384, 1)
lstm_pipe_kernel(const float* __restrict__ x,
                 const float* __restrict__ Wih0,
                 const float* __restrict__ Whh0,
                 const float* __restrict__ b0,
                 const float* __restrict__ Wih1,
                 const float* __restrict__ Whh1,
                 const float* __restrict__ b1,
                 const float* __restrict__ h0in,
                 const float* __restrict__ c0in,
                 const float* __restrict__ headw,
                 const float* __restrict__ headb,
                 float* __restrict__ out,
                 int L)
{
    __shared__ Smem sm;
    const int tid = threadIdx.x;
    uint32_t rank;
    asm("mov.u32 %0, %%cluster_ctarank;" : "=r"(rank));
    const int batch = blockIdx.x / 3;

    if (tid == 0) {
#pragma unroll
        for (int s = 0; s < NSLOT; s++) {
            mbar_init(saddr(&sm.fullA[s]), H);   // 96 per-thread remote arrivals
            mbar_init(saddr(&sm.emptyA[s]), 1);  // single ack
            mbar_init(saddr(&sm.fullB[s]), G);   // 384 per-thread remote arrivals
            mbar_init(saddr(&sm.emptyB[s]), 1);  // single ack
        }
    }

    // Load this thread's weight row into registers (packed f32x2 pairs).
    const float* Wr = (rank == 0) ? (Whh0 + tid * H)
                    : (rank == 1) ? (Wih1 + tid * H)
                                  : (Whh1 + tid * H);
    unsigned long long w2[48];
    {
        const float4* w4 = (const float4*)Wr;
#pragma unroll
        for (int k = 0; k < 24; k++) {
            float4 v = w4[k];
            w2[2 * k]     = ((unsigned long long)__float_as_uint(v.y) << 32) | __float_as_uint(v.x);
            w2[2 * k + 1] = ((unsigned long long)__float_as_uint(v.w) << 32) | __float_as_uint(v.z);
        }
    }
    float bias  = (rank == 0) ? b0[tid] : (rank == 1) ? b1[tid] : 0.f;
    float wih0v = (rank == 0) ? Wih0[tid] : 0.f;
    float c = 0.f, hw = 0.f, hb = 0.f;
    if (tid < H) {
        if (rank == 0) { c = c0in[tid];     sm.hloc[tid] = h0in[tid]; }
        if (rank == 2) { c = c0in[H + tid]; sm.hloc[tid] = h0in[H + tid];
                         hw = headw[tid];   hb = headb[0]; }
    }
    __syncthreads();
    // All barriers initialized + initial states visible before any remote op.
    asm volatile("barrier.cluster.arrive.aligned;" ::: "memory");
    asm volatile("barrier.cluster.wait.aligned;" ::: "memory");

    if (rank == 0) {
        // ---- stage 0: layer-0 recurrence ----
        const float* xb = x + batch * L;
        uint32_t rSlotA = mapa_rank(saddr(&sm.slotA[0][0]), 1);
        uint32_t rFullA = mapa_rank(saddr(&sm.fullA[0]), 1);
        uint32_t eA     = saddr(&sm.emptyA[0]);
        for (int t = 0; t < L; t++) {
            int s = t & (NSLOT - 1);
            float xt = __ldg(&xb[t]);
            float zv = __fmaf_rn(xt, wih0v, bias) + dot96(w2, sm.hloc);
            sm.z[tid] = zv;
            __syncthreads();
            if (tid < H) {
                float ig = sigf(sm.z[tid]);
                float fg = sigf(sm.z[H + tid]);
                float gg = tanh_fast(sm.z[2 * H + tid]);
                float og = sigf(sm.z[3 * H + tid]);
                c = __fmaf_rn(fg, c, ig * gg);
                float h = og * tanh_fast(c);
                sm.hloc[tid] = h;
                // producer-side empty wait: fresh barrier passes at parity 1
                wait_par(eA + 8u * s, 1u ^ ((uint32_t)(t >> 2) & 1u));
                st_remote(rSlotA + 4u * (s * H + tid), h);
                arrive_remote(rFullA + 8u * s);
            }
            __syncthreads();
        }
    } else if (rank == 1) {
        // ---- stage 1: u = W_ih_1 * h0 + b1 ----
        uint32_t fA      = saddr(&sm.fullA[0]);
        uint32_t eB      = saddr(&sm.emptyB[0]);
        uint32_t rEmptyA = mapa_rank(saddr(&sm.emptyA[0]), 0);
        uint32_t rSlotB  = mapa_rank(saddr(&sm.slotB[0][0]), 2);
        uint32_t rFullB  = mapa_rank(saddr(&sm.fullB[0]), 2);
        for (int t = 0; t < L; t++) {
            int s = t & (NSLOT - 1);
            uint32_t fp = (uint32_t)(t >> 2) & 1u;
            wait_par(fA + 8u * s, fp);
            float u = bias + dot96(w2, sm.slotA[s]);
            __syncthreads();                       // all reads of slotA[s] done
            if (tid == 0) arrive_remote(rEmptyA + 8u * s);
            wait_par(eB + 8u * s, 1u ^ fp);        // producer side for ring B
            st_remote(rSlotB + 4u * (s * G + tid), u);
            arrive_remote(rFullB + 8u * s);
        }
    } else {
        // ---- stage 2: v = W_hh_1 * h1 ; combine ; head ----
        uint32_t fB      = saddr(&sm.fullB[0]);
        uint32_t rEmptyB = mapa_rank(saddr(&sm.emptyB[0]), 1);
        float* yb = out + batch * L;
        const int lane = tid & 31;
        const int wrp  = tid >> 5;
        for (int t = 0; t < L; t++) {
            int s = t & (NSLOT - 1);
            uint32_t fp = (uint32_t)(t >> 2) & 1u;
            float v = dot96(w2, sm.hloc);          // overlaps with u in flight
            wait_par(fB + 8u * s, fp);
            float zv = v + sm.slotB[s][tid];
            sm.z[tid] = zv;
            __syncthreads();
            if (tid == 0) arrive_remote(rEmptyB + 8u * s);
            if (tid < H) {
                float ig = sigf(sm.z[tid]);
                float fg = sigf(sm.z[H + tid]);
                float gg = tanh_fast(sm.z[2 * H + tid]);
                float og = sigf(sm.z[3 * H + tid]);
                c = __fmaf_rn(fg, c, ig * gg);
                float h = og * tanh_fast(c);
                sm.hloc[tid] = h;
                float p = h * hw;
#pragma unroll
                for (int o = 16; o > 0; o >>= 1)
                    p += __shfl_xor_sync(0xffffffffu, p, o);
                if (lane == 0) sm.wpart[wrp] = p;
            }
            __syncthreads();
            if (tid == 0) yb[t] = sm.wpart[0] + sm.wpart[1] + sm.wpart[2] + hb;
        }
    }

    // No CTA may exit while peers can still arrive on its barriers.
    asm volatile("barrier.cluster.arrive.aligned;" ::: "memory");
    asm volatile("barrier.cluster.wait.aligned;" ::: "memory");
}

extern "C" void kernel_launch(void* const* d_in, const int* in_sizes, int n_in,
                              void* d_out, int out_size) {
    const float* x     = (const float*)d_in[0];
    const float* Wih0  = (const float*)d_in[1];
    const float* Whh0  = (const float*)d_in[2];
    const float* b0    = (const float*)d_in[3];
    const float* Wih1  = (const float*)d_in[4];
    const float* Whh1  = (const float*)d_in[5];
    const float* b1    = (const float*)d_in[6];
    const float* h0in  = (const float*)d_in[7];
    const float* c0in  = (const float*)d_in[8];
    const float* headw = (const float*)d_in[9];
    const float* headb = (const float*)d_in[10];
    float* out = (float*)d_out;
    int L = in_sizes[0] / BATCH;

    lstm_pipe_kernel<<<BATCH * 3, 384>>>(x, Wih0, Whh0, b0, Wih1, Whh1, b1,
                                         h0in, c0in, headw, headb, out, L);
}

// round 3
// speedup vs baseline: 1.5108x; 1.5108x over previous
#include <cuda_runtime.h>
#include <cstdint>

// LSTM_58514634440709: B=8, L=32768, H=96, 2 layers + head.
// 8 clusters x 3 CTAs (one cluster per sequence), 3-stage pipeline:
//   CTA0: layer-0 recurrence (W_hh_0 RF-resident)         -> h0 stream
//   CTA1: u = W_ih_1 * h0 + b1 (W_ih_1 RF-resident)       -> u stream
//   CTA2: v = W_hh_1 * h1 ; gates = u + v ; h1 ; head out
// Gate layout: warp w, lane g*8+k owns gate-row g*96 + 8w + k, so the four
// gates of h-index 8w+k live in ONE warp -> shfl combine, single bar/step.
// Transport: groups of 4 steps shipped with one cp.async.bulk (S2S cluster)
// completing on the consumer's mbarrier via tx bytes (consumer-side expect_tx).

#define H 96
#define G 384
#define BATCH 8
#define NSLOT 4

struct __align__(16) Smem {
    unsigned long long fullA[NSLOT];   // CTA1: h0 group arrived (tx)
    unsigned long long emptyA[NSLOT];  // CTA0: slotA free
    unsigned long long fullB[NSLOT];   // CTA2: u group arrived (tx)
    unsigned long long emptyB[NSLOT];  // CTA1: slotB free
    union {                            // 24576 B
        float ustage[NSLOT][4][G];     // CTA1 staging (local)
        float slotB[NSLOT][4][G];      // CTA2 inbox
    };
    union {                            // 6144 B
        float hgrp[NSLOT][4][H];       // CTA0 staging (local)
        float slotA[NSLOT][4][H];      // CTA1 inbox
    };
    float hcur[2][H];                  // CTA0 / CTA2 recurrent state (ping-pong)
    float wpart[4][12];                // CTA2 head partials per sub-step
};

__device__ __forceinline__ uint32_t saddr(const void* p) {
    return (uint32_t)__cvta_generic_to_shared(p);
}
__device__ __forceinline__ uint32_t mapa_rank(uint32_t a, uint32_t r) {
    uint32_t d;
    asm("mapa.shared::cluster.u32 %0, %1, %2;" : "=r"(d) : "r"(a), "r"(r));
    return d;
}
__device__ __forceinline__ void mbar_init(uint32_t a, uint32_t cnt) {
    asm volatile("mbarrier.init.shared.b64 [%0], %1;" :: "r"(a), "r"(cnt) : "memory");
}
__device__ __forceinline__ void expect_tx(uint32_t a, uint32_t bytes) {
    asm volatile("mbarrier.arrive.expect_tx.shared.b64 _, [%0], %1;"
                 :: "r"(a), "r"(bytes) : "memory");
}
__device__ __forceinline__ void arrive_remote(uint32_t a) {
    asm volatile("mbarrier.arrive.release.cluster.shared::cluster.b64 _, [%0];"
                 :: "r"(a) : "memory");
}
__device__ __forceinline__ void fence_proxy() {
    asm volatile("fence.proxy.async.shared::cta;" ::: "memory");
}
__device__ __forceinline__ void bulk_s2s(uint32_t dst, uint32_t src,
                                         uint32_t bytes, uint32_t mbar) {
    asm volatile(
        "cp.async.bulk.shared::cluster.shared::cta.mbarrier::complete_tx::bytes "
        "[%0], [%1], %2, [%3];"
        :: "r"(dst), "r"(src), "r"(bytes), "r"(mbar) : "memory");
}
__device__ __forceinline__ void wait_par(uint32_t a, uint32_t par) {
    asm volatile(
        "{\n\t"
        ".reg .pred P;\n\t"
        "WLOOP_%=:\n\t"
        "mbarrier.try_wait.parity.acquire.cluster.shared::cta.b64 P, [%0], %1, 0x989680;\n\t"
        "@P bra WDONE_%=;\n\t"
        "bra WLOOP_%=;\n\t"
        "WDONE_%=:\n\t"
        "}" :: "r"(a), "r"(par) : "memory");
}

#define FMA2(acc, w, h) asm("fma.rn.f32x2 %0, %1, %2, %0;" : "+l"(acc) : "l"(w), "l"(h))
#define ADD2(a, b)      asm("add.rn.f32x2 %0, %0, %1;" : "+l"(a) : "l"(b))

__device__ __forceinline__ float sigf(float x) {
    return __fdividef(1.f, 1.f + __expf(-x));
}
__device__ __forceinline__ float tanh_fast(float x) {
    return __fmaf_rn(2.f, __fdividef(1.f, 1.f + __expf(-2.f * x)), -1.f);
}

__device__ __forceinline__ float dot96(const unsigned long long* w2, const float* h) {
    const ulonglong2* h2 = (const ulonglong2*)h;
    unsigned long long a0 = 0ull, a1 = 0ull, a2 = 0ull, a3 = 0ull;
#pragma unroll
    for (int kk = 0; kk < 12; kk++) {
        ulonglong2 p = h2[2 * kk];
        ulonglong2 q = h2[2 * kk + 1];
        FMA2(a0, w2[4 * kk + 0], p.x);
        FMA2(a1, w2[4 * kk + 1], p.y);
        FMA2(a2, w2[4 * kk + 2], q.x);
        FMA2(a3, w2[4 * kk + 3], q.y);
    }
    ADD2(a0, a1); ADD2(a2, a3); ADD2(a0, a2);
    float lo = __uint_as_float((unsigned)(a0 & 0xffffffffull));
    float hi = __uint_as_float((unsigned)(a0 >> 32));
    return lo + hi;
}

__global__ void __cluster_dims__(3, 1, 1) __launch_bounds__(384, 1)
lstm_pipe_kernel(const float* __restrict__ x,
                 const float* __restrict__ Wih0,
                 const float* __restrict__ Whh0,
                 const float* __restrict__ b0,
                 const float* __restrict__ Wih1,
                 const float* __restrict__ Whh1,
                 const float* __restrict__ b1,
                 const float* __restrict__ h0in,
                 const float* __restrict__ c0in,
                 const float* __restrict__ headw,
                 const float* __restrict__ headb,
                 float* __restrict__ out,
                 int L)
{
    __shared__ Smem sm;
    const int tid = threadIdx.x;
    uint32_t rank;
    asm("mov.u32 %0, %%cluster_ctarank;" : "=r"(rank));
    const int batch = blockIdx.x / 3;
    const int lane = tid & 31;
    const int w    = tid >> 5;
    const int k    = lane & 7;
    const int g    = lane >> 3;
    const int idx  = w * 8 + k;      // h-index owned by g==0 lanes
    const int row  = g * H + idx;    // gate row computed by this thread

    if (tid == 0) {
#pragma unroll
        for (int s = 0; s < NSLOT; s++) {
            mbar_init(saddr(&sm.fullA[s]), 1);
            mbar_init(saddr(&sm.emptyA[s]), 1);
            mbar_init(saddr(&sm.fullB[s]), 1);
            mbar_init(saddr(&sm.emptyB[s]), 1);
        }
    }

    const float* Wr = (rank == 0) ? (Whh0 + row * H)
                    : (rank == 1) ? (Wih1 + row * H)
                                  : (Whh1 + row * H);
    unsigned long long w2[48];
    {
        const float4* w4 = (const float4*)Wr;
#pragma unroll
        for (int kk = 0; kk < 24; kk++) {
            float4 v = w4[kk];
            w2[2 * kk]     = ((unsigned long long)__float_as_uint(v.y) << 32) | __float_as_uint(v.x);
            w2[2 * kk + 1] = ((unsigned long long)__float_as_uint(v.w) << 32) | __float_as_uint(v.z);
        }
    }
    float bias = (rank == 0) ? b0[row] : (rank == 1) ? b1[row] : 0.f;
    float wx   = (rank == 0) ? Wih0[row] : 0.f;
    float c = 0.f, hw = 0.f;
    if (g == 0) {
        if (rank == 0) c = c0in[idx];
        if (rank == 2) { c = c0in[H + idx]; hw = headw[idx]; }
    }
    float hb = (rank == 2) ? headb[0] : 0.f;
    if (tid < H) {
        if (rank == 0) sm.hcur[0][tid] = h0in[tid];
        if (rank == 2) sm.hcur[0][tid] = h0in[H + tid];
    }
    __syncthreads();
    asm volatile("barrier.cluster.arrive.aligned;" ::: "memory");
    asm volatile("barrier.cluster.wait.aligned;" ::: "memory");

    if (rank == 0) {
        const float* xb = x + batch * L;
        uint32_t rSlotA = mapa_rank(saddr(&sm.slotA[0][0][0]), 1);
        uint32_t rFullA = mapa_rank(saddr(&sm.fullA[0]), 1);
        uint32_t eA     = saddr(&sm.emptyA[0]);
        for (int t = 0; t < L; t += 4) {
            int gi = t >> 2;
            int s  = gi & (NSLOT - 1);
            uint32_t fp = (uint32_t)(gi >> 2) & 1u;
            float4 xv = __ldg((const float4*)(xb + t));
#define L0STEP(j, xc, rb, wb)                                                  \
            {                                                                  \
                float zv = __fmaf_rn(xc, wx, bias) + dot96(w2, sm.hcur[rb]);   \
                float a  = (g == 2) ? tanh_fast(zv) : sigf(zv);                \
                float ig = __shfl_sync(0xffffffffu, a, k);                     \
                float fg = __shfl_sync(0xffffffffu, a, k + 8);                 \
                float gg = __shfl_sync(0xffffffffu, a, k + 16);                \
                float og = __shfl_sync(0xffffffffu, a, k + 24);                \
                if (g == 0) {                                                  \
                    c = __fmaf_rn(fg, c, ig * gg);                             \
                    float hv = og * tanh_fast(c);                              \
                    sm.hcur[wb][idx]   = hv;                                   \
                    sm.hgrp[s][j][idx] = hv;                                   \
                }                                                              \
                __syncthreads();                                               \
            }
            L0STEP(0, xv.x, 0, 1)
            L0STEP(1, xv.y, 1, 0)
            L0STEP(2, xv.z, 0, 1)
            L0STEP(3, xv.w, 1, 0)
#undef L0STEP
            if (tid == 0) {
                fence_proxy();
                wait_par(eA + 8u * s, 1u ^ fp);
                bulk_s2s(rSlotA + 1536u * s, saddr(&sm.hgrp[s][0][0]),
                         1536u, rFullA + 8u * s);
            }
        }
    } else if (rank == 1) {
        uint32_t fA      = saddr(&sm.fullA[0]);
        uint32_t eB      = saddr(&sm.emptyB[0]);
        uint32_t rEmptyA = mapa_rank(saddr(&sm.emptyA[0]), 0);
        uint32_t rSlotB  = mapa_rank(saddr(&sm.slotB[0][0][0]), 2);
        uint32_t rFullB  = mapa_rank(saddr(&sm.fullB[0]), 2);
        for (int t = 0; t < L; t += 4) {
            int gi = t >> 2;
            int s  = gi & (NSLOT - 1);
            uint32_t fp = (uint32_t)(gi >> 2) & 1u;
            if (tid == 0) expect_tx(fA + 8u * s, 1536u);
            wait_par(fA + 8u * s, fp);
            float u0 = bias + dot96(w2, sm.slotA[s][0]);
            float u1 = bias + dot96(w2, sm.slotA[s][1]);
            float u2 = bias + dot96(w2, sm.slotA[s][2]);
            float u3 = bias + dot96(w2, sm.slotA[s][3]);
            sm.ustage[s][0][row] = u0;
            sm.ustage[s][1][row] = u1;
            sm.ustage[s][2][row] = u2;
            sm.ustage[s][3][row] = u3;
            __syncthreads();
            if (tid == 0) {
                arrive_remote(rEmptyA + 8u * s);
                fence_proxy();
                wait_par(eB + 8u * s, 1u ^ fp);
                bulk_s2s(rSlotB + 6144u * s, saddr(&sm.ustage[s][0][0]),
                         6144u, rFullB + 8u * s);
            }
        }
    } else {
        uint32_t fB      = saddr(&sm.fullB[0]);
        uint32_t rEmptyB = mapa_rank(saddr(&sm.emptyB[0]), 1);
        float* yb = out + batch * L;
        for (int t = 0; t < L; t += 4) {
            int gi = t >> 2;
            int s  = gi & (NSLOT - 1);
            uint32_t fp = (uint32_t)(gi >> 2) & 1u;
            if (tid == 0) expect_tx(fB + 8u * s, 6144u);
#define L2STEP(j, rb, wb)                                                      \
            {                                                                  \
                float v = dot96(w2, sm.hcur[rb]);                              \
                if (j == 0) wait_par(fB + 8u * s, fp);                         \
                float zv = v + sm.slotB[s][j][row];                            \
                float a  = (g == 2) ? tanh_fast(zv) : sigf(zv);                \
                float ig = __shfl_sync(0xffffffffu, a, k);                     \
                float fg = __shfl_sync(0xffffffffu, a, k + 8);                 \
                float gg = __shfl_sync(0xffffffffu, a, k + 16);                \
                float og = __shfl_sync(0xffffffffu, a, k + 24);                \
                if (g == 0) {                                                  \
                    c = __fmaf_rn(fg, c, ig * gg);                             \
                    float hv = og * tanh_fast(c);                              \
                    sm.hcur[wb][idx] = hv;                                     \
                    float p = hv * hw;                                         \
                    p += __shfl_xor_sync(0xffu, p, 1);                         \
                    p += __shfl_xor_sync(0xffu, p, 2);                         \
                    p += __shfl_xor_sync(0xffu, p, 4);                         \
                    if (k == 0) sm.wpart[j][w] = p;                            \
                }                                                              \
                __syncthreads();                                               \
                if (lane == 31 && w == 8 + j) {                                \
                    const float4* wp = (const float4*)sm.wpart[j];             \
                    float4 p0 = wp[0], p1 = wp[1], p2 = wp[2];                 \
                    float y = hb + p0.x + p0.y + p0.z + p0.w                   \
                                 + p1.x + p1.y + p1.z + p1.w                   \
                                 + p2.x + p2.y + p2.z + p2.w;                  \
                    yb[t + j] = y;                                             \
                }                                                              \
            }
            L2STEP(0, 0, 1)
            L2STEP(1, 1, 0)
            L2STEP(2, 0, 1)
            L2STEP(3, 1, 0)
#undef L2STEP
            if (tid == 0) arrive_remote(rEmptyB + 8u * s);
        }
    }

    asm volatile("barrier.cluster.arrive.aligned;" ::: "memory");
    asm volatile("barrier.cluster.wait.aligned;" ::: "memory");
}

extern "C" void kernel_launch(void* const* d_in, const int* in_sizes, int n_in,
                              void* d_out, int out_size) {
    const float* x     = (const float*)d_in[0];
    const float* Wih0  = (const float*)d_in[1];
    const float* Whh0  = (const float*)d_in[2];
    const float* b0    = (const float*)d_in[3];
    const float* Wih1  = (const float*)d_in[4];
    const float* Whh1  = (const float*)d_in[5];
    const float* b1    = (const float*)d_in[6];
    const float* h0in  = (const float*)d_in[7];
    const float* c0in  = (const float*)d_in[8];
    const float* headw = (const float*)d_in[9];
    const float* headb = (const float*)d_in[10];
    float* out = (float*)d_out;
    int L = in_sizes[0] / BATCH;

    lstm_pipe_kernel<<<BATCH * 3, 384>>>(x, Wih0, Whh0, b0, Wih1, Whh1, b1,
                                         h0in, c0in, headw, headb, out, L);
}

// round 5
// speedup vs baseline: 1.7690x; 1.1709x over previous
#include <cuda_runtime.h>
#include <cstdint>

// LSTM_58514634440709: B=8, L=32768, H=96, 2 layers + head.
// 8 clusters x 3 CTAs, 3-stage pipeline (see R2). R3 changes:
//  - tanh.approx.f32 activations (sigmoid via tanh identity)
//  - transport issued by idle lane (tid 24) during next group's c-window
//  - x prefetch via smem double buffer (tid 25)
//  - head reduction deferred 2 steps to idle lanes (lane 25 / tid 26)

#define H 96
#define G 384
#define BATCH 8
#define NSLOT 4

struct __align__(16) Smem {
    unsigned long long fullA[NSLOT];
    unsigned long long emptyA[NSLOT];
    unsigned long long fullB[NSLOT];
    unsigned long long emptyB[NSLOT];
    union {                            // 24576 B
        float ustage[NSLOT][4][G];     // CTA1 staging
        float slotB[NSLOT][4][G];      // CTA2 inbox
    };
    union {                            // 6144 B
        float hgrp[NSLOT][4][H];       // CTA0 staging
        float slotA[NSLOT][4][H];      // CTA1 inbox
    };
    float hcur[2][H];                  // recurrent state ping-pong
    float wpart[2][16];                // CTA2 head partials (parity buffered)
    float hwsm[H];                     // CTA2 head weights
    float xstage[2][4];                // CTA0 x prefetch
};

__device__ __forceinline__ uint32_t saddr(const void* p) {
    return (uint32_t)__cvta_generic_to_shared(p);
}
__device__ __forceinline__ uint32_t mapa_rank(uint32_t a, uint32_t r) {
    uint32_t d;
    asm("mapa.shared::cluster.u32 %0, %1, %2;" : "=r"(d) : "r"(a), "r"(r));
    return d;
}
__device__ __forceinline__ void mbar_init(uint32_t a, uint32_t cnt) {
    asm volatile("mbarrier.init.shared.b64 [%0], %1;" :: "r"(a), "r"(cnt) : "memory");
}
__device__ __forceinline__ void expect_tx(uint32_t a, uint32_t bytes) {
    asm volatile("mbarrier.arrive.expect_tx.shared.b64 _, [%0], %1;"
                 :: "r"(a), "r"(bytes) : "memory");
}
__device__ __forceinline__ void arrive_remote(uint32_t a) {
    asm volatile("mbarrier.arrive.release.cluster.shared::cluster.b64 _, [%0];"
                 :: "r"(a) : "memory");
}
__device__ __forceinline__ void fence_proxy() {
    asm volatile("fence.proxy.async.shared::cta;" ::: "memory");
}
__device__ __forceinline__ void bulk_s2s(uint32_t dst, uint32_t src,
                                         uint32_t bytes, uint32_t mbar) {
    asm volatile(
        "cp.async.bulk.shared::cluster.shared::cta.mbarrier::complete_tx::bytes "
        "[%0], [%1], %2, [%3];"
        :: "r"(dst), "r"(src), "r"(bytes), "r"(mbar) : "memory");
}
__device__ __forceinline__ void wait_par(uint32_t a, uint32_t par) {
    asm volatile(
        "{\n\t"
        ".reg .pred P;\n\t"
        "WLOOP_%=:\n\t"
        "mbarrier.try_wait.parity.acquire.cluster.shared::cta.b64 P, [%0], %1, 0x989680;\n\t"
        "@P bra WDONE_%=;\n\t"
        "bra WLOOP_%=;\n\t"
        "WDONE_%=:\n\t"
        "}" :: "r"(a), "r"(par) : "memory");
}

#define FMA2(acc, w, h) asm("fma.rn.f32x2 %0, %1, %2, %0;" : "+l"(acc) : "l"(w), "l"(h))
#define ADD2(a, b)      asm("add.rn.f32x2 %0, %0, %1;" : "+l"(a) : "l"(b))

__device__ __forceinline__ float tanhap(float x) {
    float y;
    asm("tanh.approx.f32 %0, %1;" : "=f"(y) : "f"(x));
    return y;
}

// dot(w_row[96], h[96]) + init, packed f32x2 FMAs, broadcast smem reads.
__device__ __forceinline__ float dot96i(const unsigned long long* w2,
                                        const float* h, float init) {
    const ulonglong2* h2 = (const ulonglong2*)h;
    unsigned long long a0 = (unsigned long long)__float_as_uint(init);
    unsigned long long a1 = 0ull, a2 = 0ull, a3 = 0ull;
#pragma unroll
    for (int kk = 0; kk < 12; kk++) {
        ulonglong2 p = h2[2 * kk];
        ulonglong2 q = h2[2 * kk + 1];
        FMA2(a0, w2[4 * kk + 0], p.x);
        FMA2(a1, w2[4 * kk + 1], p.y);
        FMA2(a2, w2[4 * kk + 2], q.x);
        FMA2(a3, w2[4 * kk + 3], q.y);
    }
    ADD2(a0, a1); ADD2(a2, a3); ADD2(a0, a2);
    float lo, hi;
    asm("mov.b64 {%0, %1}, %2;" : "=f"(lo), "=f"(hi) : "l"(a0));
    return lo + hi;
}

__global__ void __cluster_dims__(3, 1, 1) __launch_bounds__(384, 1)
lstm_pipe_kernel(const float* __restrict__ x,
                 const float* __restrict__ Wih0,
                 const float* __restrict__ Whh0,
                 const float* __restrict__ b0,
                 const float* __restrict__ Wih1,
                 const float* __restrict__ Whh1,
                 const float* __restrict__ b1,
                 const float* __restrict__ h0in,
                 const float* __restrict__ c0in,
                 const float* __restrict__ headw,
                 const float* __restrict__ headb,
                 float* __restrict__ out,
                 int L)
{
    __shared__ Smem sm;
    const int tid = threadIdx.x;
    uint32_t rank;
    asm("mov.u32 %0, %%cluster_ctarank;" : "=r"(rank));
    const int batch = blockIdx.x / 3;
    const int lane = tid & 31;
    const int w    = tid >> 5;
    const int k    = lane & 7;
    const int g    = lane >> 3;
    const int idx  = w * 8 + k;
    const int row  = g * H + idx;

    if (tid == 0) {
#pragma unroll
        for (int s = 0; s < NSLOT; s++) {
            mbar_init(saddr(&sm.fullA[s]), 1);
            mbar_init(saddr(&sm.emptyA[s]), 1);
            mbar_init(saddr(&sm.fullB[s]), 1);
            mbar_init(saddr(&sm.emptyB[s]), 1);
        }
    }

    const float* Wr = (rank == 0) ? (Whh0 + row * H)
                    : (rank == 1) ? (Wih1 + row * H)
                                  : (Whh1 + row * H);
    unsigned long long w2[48];
    {
        const float4* w4 = (const float4*)Wr;
#pragma unroll
        for (int kk = 0; kk < 24; kk++) {
            float4 v = w4[kk];
            w2[2 * kk]     = ((unsigned long long)__float_as_uint(v.y) << 32) | __float_as_uint(v.x);
            w2[2 * kk + 1] = ((unsigned long long)__float_as_uint(v.w) << 32) | __float_as_uint(v.z);
        }
    }
    float bias = (rank == 0) ? b0[row] : (rank == 1) ? b1[row] : 0.f;
    float wx   = (rank == 0) ? Wih0[row] : 0.f;
    float c = 0.f;
    if (g == 0) {
        if (rank == 0) c = c0in[idx];
        if (rank == 2) c = c0in[H + idx];
    }
    float hb = (rank == 2) ? headb[0] : 0.f;
    if (tid < H) {
        if (rank == 0) sm.hcur[0][tid] = h0in[tid];
        if (rank == 2) { sm.hcur[0][tid] = h0in[H + tid]; sm.hwsm[tid] = headw[tid]; }
    }
    if (rank == 0 && tid == 25) {
        float4 x0 = __ldg((const float4*)(x + batch * L));
        *(float4*)sm.xstage[0] = x0;
    }
    __syncthreads();
    asm volatile("barrier.cluster.arrive.aligned;" ::: "memory");
    asm volatile("barrier.cluster.wait.aligned;" ::: "memory");

    const int ng = L >> 2;

    if (rank == 0) {
        const float* xb = x + batch * L;
        uint32_t rSlotA = mapa_rank(saddr(&sm.slotA[0][0][0]), 1);
        uint32_t rFullA = mapa_rank(saddr(&sm.fullA[0]), 1);
        uint32_t eA     = saddr(&sm.emptyA[0]);
        for (int gi = 0; gi < ng; gi++) {
            int s = gi & (NSLOT - 1);
            float4 xv = *(const float4*)sm.xstage[gi & 1];
#define L0STEP(j, xc, rb, wb, EXTRAS)                                          \
            {                                                                  \
                float zv = dot96i(w2, sm.hcur[rb], __fmaf_rn(xc, wx, bias));   \
                float arg = (g == 2) ? zv : 0.5f * zv;                         \
                float th = tanhap(arg);                                        \
                float a  = (g == 2) ? th : __fmaf_rn(0.5f, th, 0.5f);          \
                float ig = __shfl_sync(0xffffffffu, a, k);                     \
                float fg = __shfl_sync(0xffffffffu, a, k + 8);                 \
                float gg = __shfl_sync(0xffffffffu, a, k + 16);                \
                float og = __shfl_sync(0xffffffffu, a, k + 24);                \
                EXTRAS                                                         \
                if (g == 0) {                                                  \
                    c = __fmaf_rn(fg, c, ig * gg);                             \
                    float hv = og * tanhap(c);                                 \
                    sm.hcur[wb][idx]   = hv;                                   \
                    sm.hgrp[s][j][idx] = hv;                                   \
                }                                                              \
                __syncthreads();                                               \
            }
            L0STEP(0, xv.x, 0, 1,
                if (tid == 25 && gi + 1 < ng) {
                    float4 nx = __ldg((const float4*)(xb + 4 * (gi + 1)));
                    *(float4*)sm.xstage[(gi + 1) & 1] = nx;
                }
                if (tid == 24 && gi > 0) {
                    int ps = (gi - 1) & (NSLOT - 1);
                    uint32_t pfp = (uint32_t)((gi - 1) >> 2) & 1u;
                    fence_proxy();
                    wait_par(eA + 8u * ps, 1u ^ pfp);
                    bulk_s2s(rSlotA + 1536u * ps, saddr(&sm.hgrp[ps][0][0]),
                             1536u, rFullA + 8u * ps);
                }
            )
            L0STEP(1, xv.y, 1, 0, )
            L0STEP(2, xv.z, 0, 1, )
            L0STEP(3, xv.w, 1, 0, )
#undef L0STEP
        }
        if (tid == 24) {   // ship final group
            int ps = (ng - 1) & (NSLOT - 1);
            uint32_t pfp = (uint32_t)((ng - 1) >> 2) & 1u;
            fence_proxy();
            wait_par(eA + 8u * ps, 1u ^ pfp);
            bulk_s2s(rSlotA + 1536u * ps, saddr(&sm.hgrp[ps][0][0]),
                     1536u, rFullA + 8u * ps);
        }
    } else if (rank == 1) {
        uint32_t fA      = saddr(&sm.fullA[0]);
        uint32_t eB      = saddr(&sm.emptyB[0]);
        uint32_t rEmptyA = mapa_rank(saddr(&sm.emptyA[0]), 0);
        uint32_t rSlotB  = mapa_rank(saddr(&sm.slotB[0][0][0]), 2);
        uint32_t rFullB  = mapa_rank(saddr(&sm.fullB[0]), 2);
        for (int gi = 0; gi < ng; gi++) {
            int s = gi & (NSLOT - 1);
            uint32_t fp = (uint32_t)(gi >> 2) & 1u;
            if (gi > 0) {
                int ps = (gi - 1) & (NSLOT - 1);
                uint32_t pfp = (uint32_t)((gi - 1) >> 2) & 1u;
                if (tid == 0) arrive_remote(rEmptyA + 8u * ps);
                if (tid == 32) {
                    fence_proxy();
                    wait_par(eB + 8u * ps, 1u ^ pfp);
                    bulk_s2s(rSlotB + 6144u * ps, saddr(&sm.ustage[ps][0][0]),
                             6144u, rFullB + 8u * ps);
                }
            }
            if (tid == 64) expect_tx(fA + 8u * s, 1536u);
            wait_par(fA + 8u * s, fp);
            float u0 = dot96i(w2, sm.slotA[s][0], bias);
            float u1 = dot96i(w2, sm.slotA[s][1], bias);
            float u2 = dot96i(w2, sm.slotA[s][2], bias);
            float u3 = dot96i(w2, sm.slotA[s][3], bias);
            sm.ustage[s][0][row] = u0;
            sm.ustage[s][1][row] = u1;
            sm.ustage[s][2][row] = u2;
            sm.ustage[s][3][row] = u3;
            __syncthreads();
        }
        if (tid == 32) {   // ship final group
            int ps = (ng - 1) & (NSLOT - 1);
            uint32_t pfp = (uint32_t)((ng - 1) >> 2) & 1u;
            fence_proxy();
            wait_par(eB + 8u * ps, 1u ^ pfp);
            bulk_s2s(rSlotB + 6144u * ps, saddr(&sm.ustage[ps][0][0]),
                     6144u, rFullB + 8u * ps);
        }
    } else {
        uint32_t fB      = saddr(&sm.fullB[0]);
        uint32_t rEmptyB = mapa_rank(saddr(&sm.emptyB[0]), 1);
        float* yb = out + batch * L;
        for (int gi = 0; gi < ng; gi++) {
            int s = gi & (NSLOT - 1);
            uint32_t fp = (uint32_t)(gi >> 2) & 1u;
            if (tid == 0 && gi > 0)
                arrive_remote(rEmptyB + 8u * ((gi - 1) & (NSLOT - 1)));
            if (tid == 64) expect_tx(fB + 8u * s, 6144u);
#define L2STEP(j, rb, wb)                                                      \
            {                                                                  \
                int t = 4 * gi + j;                                            \
                float zv;                                                      \
                if (j == 0) {                                                  \
                    float v = dot96i(w2, sm.hcur[rb], 0.f);                    \
                    wait_par(fB + 8u * s, fp);                                 \
                    zv = v + sm.slotB[s][0][row];                              \
                } else {                                                       \
                    float uv = sm.slotB[s][j][row];                            \
                    zv = dot96i(w2, sm.hcur[rb], uv);                          \
                }                                                              \
                float arg = (g == 2) ? zv : 0.5f * zv;                         \
                float th = tanhap(arg);                                        \
                float a  = (g == 2) ? th : __fmaf_rn(0.5f, th, 0.5f);          \
                float ig = __shfl_sync(0xffffffffu, a, k);                     \
                float fg = __shfl_sync(0xffffffffu, a, k + 8);                 \
                float gg = __shfl_sync(0xffffffffu, a, k + 16);                \
                float og = __shfl_sync(0xffffffffu, a, k + 24);                \
                if (g == 0) {                                                  \
                    c = __fmaf_rn(fg, c, ig * gg);                             \
                    float hv = og * tanhap(c);                                 \
                    sm.hcur[wb][idx] = hv;                                     \
                }                                                              \
                if (lane == 25 && t >= 1) {                                    \
                    const float4* hp = (const float4*)&sm.hcur[rb][8 * w];     \
                    const float4* wp = (const float4*)&sm.hwsm[8 * w];         \
                    float4 hA = hp[0], hB = hp[1];                             \
                    float4 wA = wp[0], wB = wp[1];                             \
                    float p = hA.x * wA.x + hA.y * wA.y + hA.z * wA.z          \
                            + hA.w * wA.w + hB.x * wB.x + hB.y * wB.y          \
                            + hB.z * wB.z + hB.w * wB.w;                       \
                    sm.wpart[(t - 1) & 1][w] = p;                              \
                }                                                              \
                if (tid == 26 && t >= 2) {                                     \
                    const float4* q = (const float4*)sm.wpart[t & 1];          \
                    float4 qa = q[0], qb = q[1], qc = q[2];                    \
                    yb[t - 2] = hb + qa.x + qa.y + qa.z + qa.w                 \
                                   + qb.x + qb.y + qb.z + qb.w                 \
                                   + qc.x + qc.y + qc.z + qc.w;                \
                }                                                              \
                __syncthreads();                                               \
            }
            L2STEP(0, 0, 1)
            L2STEP(1, 1, 0)
            L2STEP(2, 0, 1)
            L2STEP(3, 1, 0)
#undef L2STEP
        }
        // drain: y(L-2), y(L-1)
        if (lane == 25) {   // partial of y(L-1); h(L-1) is in hcur[0]
            const float4* hp = (const float4*)&sm.hcur[0][8 * w];
            const float4* wp = (const float4*)&sm.hwsm[8 * w];
            float4 hA = hp[0], hB = hp[1];
            float4 wA = wp[0], wB = wp[1];
            float p = hA.x * wA.x + hA.y * wA.y + hA.z * wA.z + hA.w * wA.w
                    + hB.x * wB.x + hB.y * wB.y + hB.z * wB.z + hB.w * wB.w;
            sm.wpart[1][w] = p;
        }
        if (tid == 26) {
            const float4* q = (const float4*)sm.wpart[0];
            float4 qa = q[0], qb = q[1], qc = q[2];
            yb[L - 2] = hb + qa.x + qa.y + qa.z + qa.w
                           + qb.x + qb.y + qb.z + qb.w
                           + qc.x + qc.y + qc.z + qc.w;
        }
        __syncthreads();
        if (tid == 26) {
            const float4* q = (const float4*)sm.wpart[1];
            float4 qa = q[0], qb = q[1], qc = q[2];
            yb[L - 1] = hb + qa.x + qa.y + qa.z + qa.w
                           + qb.x + qb.y + qb.z + qb.w
                           + qc.x + qc.y + qc.z + qc.w;
        }
    }

    asm volatile("barrier.cluster.arrive.aligned;" ::: "memory");
    asm volatile("barrier.cluster.wait.aligned;" ::: "memory");
}

extern "C" void kernel_launch(void* const* d_in, const int* in_sizes, int n_in,
                              void* d_out, int out_size) {
    const float* x     = (const float*)d_in[0];
    const float* Wih0  = (const float*)d_in[1];
    const float* Whh0  = (const float*)d_in[2];
    const float* b0    = (const float*)d_in[3];
    const float* Wih1  = (const float*)d_in[4];
    const float* Whh1  = (const float*)d_in[5];
    const float* b1    = (const float*)d_in[6];
    const float* h0in  = (const float*)d_in[7];
    const float* c0in  = (const float*)d_in[8];
    const float* headw = (const float*)d_in[9];
    const float* headb = (const float*)d_in[10];
    float* out = (float*)d_out;
    int L = in_sizes[0] / BATCH;

    lstm_pipe_kernel<<<BATCH * 3, 384>>>(x, Wih0, Whh0, b0, Wih1, Whh1, b1,
                                         h0in, c0in, headw, headb, out, L);
}